// round 2
// baseline (speedup 1.0000x reference)
#include <cuda_runtime.h>
#include <math.h>

#define BSZ   8
#define SEQ   512
#define DIM   768
#define NP    32
#define PE    200
#define EMB   128
#define VOCAB 30522
#define SPAN  20
#define NB    (BSZ*NP)        /* 256 span pairs */
#define NR    (NB*SPAN)       /* 5120 rows */
#define K1    1536            /* 2*DIM */

/* ---------------- scratch (no allocation allowed) ---------------- */
__device__ float g_lr[NB*K1];         /* gathered [lh,rh] rows        */
__device__ float g_Apart[4*NB*DIM];   /* split-K partials for GEMM1   */
__device__ float g_A[NB*DIM];         /* lh@W1a + rh@W1b              */
__device__ float g_P[SPAN*DIM];       /* pos@W1c + b1                 */
__device__ float g_h1[NR*DIM];
__device__ float g_pre2[NR*DIM];
__device__ float g_h2[NR*DIM];
__device__ float g_h3[NR*EMB];

__device__ __forceinline__ float gelu_exact(float x) {
    return 0.5f * x * (1.0f + erff(x * 0.70710678118654752440f));
}

/* ---------------- gather span endpoints ---------------- */
__global__ void k_gather(const float* __restrict__ hs, const int* __restrict__ pairs) {
    int p = blockIdx.x;
    int l0 = pairs[p*2 + 0];
    int r0 = pairs[p*2 + 1];
    int b  = p / NP;
    const float* hl = hs + ((size_t)b*SEQ + l0)*DIM;
    const float* hr = hs + ((size_t)b*SEQ + r0)*DIM;
    float* dst = g_lr + (size_t)p*K1;
    for (int k = threadIdx.x; k < DIM; k += blockDim.x) {
        dst[k]       = hl[k];
        dst[DIM + k] = hr[k];
    }
}

/* ---------------- P[l] = pos_emb[l] @ W1[1536:1736] + b1 ---------------- */
__global__ void k_posproj(const float* __restrict__ pos, const float* __restrict__ W1,
                          const float* __restrict__ b1) {
    __shared__ float sp[PE];
    int l = blockIdx.x;
    for (int t = threadIdx.x; t < PE; t += blockDim.x) sp[t] = pos[l*PE + t];
    __syncthreads();
    int j = threadIdx.x;  /* blockDim = 768 */
    float acc = b1[j];
    const float* w = W1 + (size_t)K1*DIM + j;
    #pragma unroll 4
    for (int t = 0; t < PE; t++) acc += sp[t] * w[(size_t)t*DIM];
    g_P[l*DIM + j] = acc;
}

/* ---------------- reduce split-K partials ---------------- */
__global__ void k_reduce4() {
    int i = blockIdx.x*blockDim.x + threadIdx.x;
    g_A[i] = g_Apart[i] + g_Apart[NB*DIM + i] + g_Apart[2*NB*DIM + i] + g_Apart[3*NB*DIM + i];
}

/* ---------------- block reduce helper ---------------- */
__device__ __forceinline__ void block_reduce2(float& s, float& sq) {
    __shared__ float ss[8], ssq[8];
    #pragma unroll
    for (int o = 16; o > 0; o >>= 1) {
        s  += __shfl_xor_sync(0xffffffffu, s,  o);
        sq += __shfl_xor_sync(0xffffffffu, sq, o);
    }
    int w = threadIdx.x >> 5;
    if ((threadIdx.x & 31) == 0) { ss[w] = s; ssq[w] = sq; }
    __syncthreads();
    s = 0.f; sq = 0.f;
    #pragma unroll
    for (int i = 0; i < 8; i++) { s += ss[i]; sq += ssq[i]; }
}

/* ---------------- h1 = LN(gelu(A[p] + P[l])) * g1 + be1 ---------------- */
__global__ void k_fuse1(const float* __restrict__ g1, const float* __restrict__ be1) {
    int r = blockIdx.x;           /* r = p*SPAN + l */
    int p = r / SPAN, l = r % SPAN;
    const float* Ap = g_A + (size_t)p*DIM;
    const float* Pl = g_P + (size_t)l*DIM;
    float v[3];
    float s = 0.f, sq = 0.f;
    int j0 = threadIdx.x;
    #pragma unroll
    for (int t = 0; t < 3; t++) {
        int j = j0 + t*256;
        float x = gelu_exact(Ap[j] + Pl[j]);
        v[t] = x; s += x; sq += x*x;
    }
    block_reduce2(s, sq);
    float mean = s * (1.0f/DIM);
    float var  = sq * (1.0f/DIM) - mean*mean;
    float rstd = rsqrtf(var + 1e-12f);
    float* out = g_h1 + (size_t)r*DIM;
    #pragma unroll
    for (int t = 0; t < 3; t++) {
        int j = j0 + t*256;
        out[j] = (v[t] - mean) * rstd * g1[j] + be1[j];
    }
}

/* ---------------- out = LN(gelu(in)) * g + be ---------------- */
__global__ void k_gelu_ln(const float* __restrict__ in, float* __restrict__ out,
                          const float* __restrict__ g, const float* __restrict__ be) {
    int r = blockIdx.x;
    const float* ip = in + (size_t)r*DIM;
    float v[3];
    float s = 0.f, sq = 0.f;
    int j0 = threadIdx.x;
    #pragma unroll
    for (int t = 0; t < 3; t++) {
        int j = j0 + t*256;
        float x = gelu_exact(ip[j]);
        v[t] = x; s += x; sq += x*x;
    }
    block_reduce2(s, sq);
    float mean = s * (1.0f/DIM);
    float var  = sq * (1.0f/DIM) - mean*mean;
    float rstd = rsqrtf(var + 1e-12f);
    float* op = out + (size_t)r*DIM;
    #pragma unroll
    for (int t = 0; t < 3; t++) {
        int j = j0 + t*256;
        op[j] = (v[t] - mean) * rstd * g[j] + be[j];
    }
}

/* ---------------- generic tiled SGEMM ----------------
 * C[M,N] = A[M,K] * B  (+bias), B either K-major [K,N] (NN) or N-major [N,K] (NT)
 * Split-K over blockIdx.z: k-offset z*K, output offset z*czstride.
 * ALIGNC: ldc multiple of 4 and all rows 16B-aligned -> float4 stores.
 */
template<int BM, int BN, int BK, int TM, int TN, bool TRANSB, bool ALIGNC>
__global__ void __launch_bounds__((BM/TM)*(BN/TN))
sgemm(int M, int N, int K,
      const float* __restrict__ A, int lda,
      const float* __restrict__ Bm, int ldb,
      float* __restrict__ C, int ldc,
      const float* __restrict__ bias, int czstride) {
    constexpr int NT_ = (BM/TM)*(BN/TN);
    constexpr int AS = BM + 4;
    constexpr int BSs = BN + 4;
    __shared__ __align__(16) float As[BK*AS];
    __shared__ __align__(16) float Bs[BK*BSs];

    const int mBase = blockIdx.y * BM;
    const int nBase = blockIdx.x * BN;
    const int k0    = blockIdx.z * K;
    C += (size_t)blockIdx.z * czstride;

    const int ty = threadIdx.x / (BN/TN);
    const int tx = threadIdx.x % (BN/TN);

    float acc[TM][TN];
    #pragma unroll
    for (int i = 0; i < TM; i++)
        #pragma unroll
        for (int j = 0; j < TN; j++) acc[i][j] = 0.f;

    constexpr int KV = BK/4;

    for (int kt = 0; kt < K; kt += BK) {
        /* load A tile (transpose into As[k][m]) */
        {
            int k4 = (threadIdx.x % KV) * 4;
            #pragma unroll
            for (int m = threadIdx.x / KV; m < BM; m += NT_/KV) {
                float4 v = *(const float4*)(A + (size_t)(mBase + m)*lda + (k0 + kt + k4));
                As[(k4+0)*AS + m] = v.x;
                As[(k4+1)*AS + m] = v.y;
                As[(k4+2)*AS + m] = v.z;
                As[(k4+3)*AS + m] = v.w;
            }
        }
        /* load B tile */
        if (TRANSB) {
            int k4 = (threadIdx.x % KV) * 4;
            #pragma unroll
            for (int n = threadIdx.x / KV; n < BN; n += NT_/KV) {
                int gn = nBase + n;
                float4 v = make_float4(0.f, 0.f, 0.f, 0.f);
                if (gn < N)
                    v = *(const float4*)(Bm + (size_t)gn*ldb + (k0 + kt + k4));
                Bs[(k4+0)*BSs + n] = v.x;
                Bs[(k4+1)*BSs + n] = v.y;
                Bs[(k4+2)*BSs + n] = v.z;
                Bs[(k4+3)*BSs + n] = v.w;
            }
        } else {
            constexpr int NV = BN/4;
            int n4 = (threadIdx.x % NV) * 4;
            #pragma unroll
            for (int k = threadIdx.x / NV; k < BK; k += NT_/NV) {
                float4 v = *(const float4*)(Bm + (size_t)(k0 + kt + k)*ldb + (nBase + n4));
                *(float4*)&Bs[k*BSs + n4] = v;
            }
        }
        __syncthreads();

        #pragma unroll
        for (int kk = 0; kk < BK; kk++) {
            float a[TM], b[TN];
            #pragma unroll
            for (int i = 0; i < TM; i += 4)
                *(float4*)&a[i] = *(const float4*)&As[kk*AS + ty*TM + i];
            #pragma unroll
            for (int j = 0; j < TN; j += 4)
                *(float4*)&b[j] = *(const float4*)&Bs[kk*BSs + tx*TN + j];
            #pragma unroll
            for (int i = 0; i < TM; i++)
                #pragma unroll
                for (int j = 0; j < TN; j++)
                    acc[i][j] += a[i] * b[j];
        }
        __syncthreads();
    }

    /* epilogue */
    #pragma unroll
    for (int i = 0; i < TM; i++) {
        int gm = mBase + ty*TM + i;
        float* crow = C + (size_t)gm*ldc;
        if (ALIGNC) {
            #pragma unroll
            for (int j = 0; j < TN; j += 4) {
                int gn = nBase + tx*TN + j;
                float4 v;
                v.x = acc[i][j+0] + (bias ? bias[gn+0] : 0.f);
                v.y = acc[i][j+1] + (bias ? bias[gn+1] : 0.f);
                v.z = acc[i][j+2] + (bias ? bias[gn+2] : 0.f);
                v.w = acc[i][j+3] + (bias ? bias[gn+3] : 0.f);
                *(float4*)(crow + gn) = v;
            }
        } else {
            #pragma unroll
            for (int j = 0; j < TN; j++) {
                int gn = nBase + tx*TN + j;
                if (gn < N)
                    crow[gn] = acc[i][j] + (bias ? bias[gn] : 0.f);
            }
        }
    }
}

/* ---------------- host launch ---------------- */
extern "C" void kernel_launch(void* const* d_in, const int* in_sizes, int n_in,
                              void* d_out, int out_size) {
    const float* hs    = (const float*)d_in[0];
    const int*   pairs = (const int*)  d_in[1];
    const float* pos   = (const float*)d_in[2];
    const float* W1    = (const float*)d_in[3];
    const float* b1    = (const float*)d_in[4];
    const float* g1    = (const float*)d_in[5];
    const float* be1   = (const float*)d_in[6];
    const float* W2    = (const float*)d_in[7];
    const float* b2    = (const float*)d_in[8];
    const float* g2    = (const float*)d_in[9];
    const float* be2   = (const float*)d_in[10];
    const float* Wp    = (const float*)d_in[11];
    const float* bp    = (const float*)d_in[12];
    const float* Wdec  = (const float*)d_in[13];
    float* out = (float*)d_out;
    (void)in_sizes; (void)n_in; (void)out_size;

    float *p_lr, *p_Apart, *p_h1, *p_pre2, *p_h2, *p_h3;
    cudaGetSymbolAddress((void**)&p_lr,    g_lr);
    cudaGetSymbolAddress((void**)&p_Apart, g_Apart);
    cudaGetSymbolAddress((void**)&p_h1,    g_h1);
    cudaGetSymbolAddress((void**)&p_pre2,  g_pre2);
    cudaGetSymbolAddress((void**)&p_h2,    g_h2);
    cudaGetSymbolAddress((void**)&p_h3,    g_h3);

    /* 1) gather [lh, rh] rows */
    k_gather<<<NB, 256>>>(hs, pairs);

    /* 2) P = pos_emb @ W1c + b1 */
    k_posproj<<<SPAN, DIM>>>(pos, W1, b1);

    /* 3) A = g_lr @ W1[0:1536]  (split-K x4 for parallelism) */
    sgemm<64,128,32,8,8,false,true><<<dim3(DIM/128, NB/64, 4), 128>>>(
        NB, DIM, K1/4, p_lr, K1, W1, DIM, p_Apart, DIM, nullptr, NB*DIM);
    k_reduce4<<<(NB*DIM)/256, 256>>>();

    /* 4) h1 = LN(gelu(A + P)) */
    k_fuse1<<<NR, 256>>>(g1, be1);

    /* 5) pre2 = h1 @ W2 + b2 ; h2 = LN(gelu(pre2)) */
    sgemm<128,128,32,8,8,false,true><<<dim3(DIM/128, NR/128, 1), 256>>>(
        NR, DIM, DIM, p_h1, DIM, W2, DIM, p_pre2, DIM, b2, 0);
    k_gelu_ln<<<NR, 256>>>(p_pre2, p_h2, g2, be2);

    /* 6) h3 = h2 @ Wp + bp */
    sgemm<64,128,32,8,8,false,true><<<dim3(EMB/128, NR/64, 1), 128>>>(
        NR, EMB, DIM, p_h2, DIM, Wp, EMB, p_h3, EMB, bp, 0);

    /* 7) out = h3 @ Wdec^T  (NT, M=5120 N=30522 K=128, unaligned ldc) */
    sgemm<128,128,32,8,8,true,false><<<dim3((VOCAB+127)/128, NR/128, 1), 256>>>(
        NR, VOCAB, EMB, p_h3, EMB, Wdec, EMB, out, VOCAB, nullptr, 0);
}

// round 4
// speedup vs baseline: 2.7942x; 2.7942x over previous
#include <cuda_runtime.h>
#include <math.h>
#include <stdint.h>

#define BSZ   8
#define SEQ   512
#define DIM   768
#define NP    32
#define PE    200
#define EMB   128
#define VOCAB 30522
#define SPAN  20
#define NB    (BSZ*NP)        /* 256 span pairs */
#define NR    (NB*SPAN)       /* 5120 rows */
#define K1    1536            /* 2*DIM */

/* ---------------- scratch (no allocation allowed) ---------------- */
__device__ float g_lr[NB*K1];
__device__ float g_Apart[4*NB*DIM];
__device__ float g_A[NB*DIM];
__device__ float g_P[SPAN*DIM];
__device__ float g_h1[NR*DIM];
__device__ float g_pre2[NR*DIM];
__device__ float g_h2[NR*DIM];
__device__ float g_h3[NR*EMB];
__device__ float g_W2T[DIM*DIM];     /* W2 transposed: [N,K] */
__device__ float g_WpT[EMB*DIM];     /* Wp transposed: [N,K] */

__device__ __forceinline__ float gelu_exact(float x) {
    return 0.5f * x * (1.0f + erff(x * 0.70710678118654752440f));
}

__device__ __forceinline__ uint32_t f2tf32(float x) {
    uint32_t r;
    asm("cvt.rna.tf32.f32 %0, %1;" : "=r"(r) : "f"(x));
    return r;
}

__device__ __forceinline__ void mma_tf32_16n8k8(float* c, const uint32_t* a, const uint32_t* b) {
    asm volatile(
        "mma.sync.aligned.m16n8k8.row.col.f32.tf32.tf32.f32 "
        "{%0,%1,%2,%3}, {%4,%5,%6,%7}, {%8,%9}, {%0,%1,%2,%3};"
        : "+f"(c[0]), "+f"(c[1]), "+f"(c[2]), "+f"(c[3])
        : "r"(a[0]), "r"(a[1]), "r"(a[2]), "r"(a[3]), "r"(b[0]), "r"(b[1]));
}

/* =================== tf32 mma.sync GEMM ===================
 * C[M, Nvalid] = A[M, K] @ Bt[Nvalid, K]^T (+bias)
 * CTA tile 128x128, BK=32, 4 warps (128 thr), warp tile 64x64.
 * A row-major (lda), Bt N-major (ldb = K stride). K multiple of 32.
 * ldc and all stored column indices even -> float2 stores are 8B aligned.
 */
#define BKP 36   /* BK + 4 pad: fragment loads hit banks 4g+t (all distinct) */

__global__ void __launch_bounds__(128, 2)
mgemm(int K, const float* __restrict__ A, int lda,
      const float* __restrict__ Bt, int ldb, int Nvalid,
      float* __restrict__ C, int ldc,
      const float* __restrict__ bias) {
    extern __shared__ __align__(16) float sm[];
    float* As = sm;                 /* [2][128*BKP] */
    float* Bs = sm + 2*128*BKP;     /* [2][128*BKP] */

    const int tid  = threadIdx.x;
    const int lane = tid & 31;
    const int wid  = tid >> 5;
    const int wr   = (wid & 1) * 64;   /* warp row offset   */
    const int wc   = (wid >> 1) * 64;  /* warp col offset   */
    const int g8   = lane >> 2;        /* group id 0..7     */
    const int t4   = lane & 3;         /* thread-in-group   */

    const int mBase = blockIdx.y * 128;
    const int nBase = blockIdx.x * 128;
    const int NK = K >> 5;

    float acc[4][8][4];
    #pragma unroll
    for (int i = 0; i < 4; i++)
        #pragma unroll
        for (int j = 0; j < 8; j++)
            #pragma unroll
            for (int q = 0; q < 4; q++) acc[i][j][q] = 0.f;

    const float* Ag = A + (size_t)mBase * lda;

    /* tile loader: 128 rows x 32 cols -> smem (tf32-rounded) */
    auto loadA = [&](int s, int kt) {
        float* dst = As + s*128*BKP;
        const float* src = Ag + kt*32;
        #pragma unroll
        for (int i = 0; i < 8; i++) {
            int idx = tid + i*128;         /* 0..1023 */
            int r = idx >> 3, c4 = (idx & 7) * 4;
            float4 v = *(const float4*)(src + (size_t)r*lda + c4);
            uint4 u; u.x=f2tf32(v.x); u.y=f2tf32(v.y); u.z=f2tf32(v.z); u.w=f2tf32(v.w);
            *(uint4*)(dst + r*BKP + c4) = u;
        }
    };
    auto loadB = [&](int s, int kt) {
        float* dst = Bs + s*128*BKP;
        #pragma unroll
        for (int i = 0; i < 8; i++) {
            int idx = tid + i*128;
            int n = idx >> 3, c4 = (idx & 7) * 4;
            int gn = nBase + n;
            float4 v = make_float4(0.f,0.f,0.f,0.f);
            if (gn < Nvalid)
                v = *(const float4*)(Bt + (size_t)gn*ldb + kt*32 + c4);
            uint4 u; u.x=f2tf32(v.x); u.y=f2tf32(v.y); u.z=f2tf32(v.z); u.w=f2tf32(v.w);
            *(uint4*)(dst + n*BKP + c4) = u;
        }
    };

    loadA(0, 0); loadB(0, 0);
    __syncthreads();

    for (int kt = 0; kt < NK; kt++) {
        int s = kt & 1;
        if (kt + 1 < NK) { loadA(s ^ 1, kt + 1); loadB(s ^ 1, kt + 1); }

        const float* as = As + s*128*BKP;
        const float* bs = Bs + s*128*BKP;
        #pragma unroll
        for (int kk = 0; kk < 32; kk += 8) {
            uint32_t af[4][4], bf[8][2];
            #pragma unroll
            for (int mt = 0; mt < 4; mt++) {
                int r0 = wr + mt*16 + g8;
                const uint32_t* p = (const uint32_t*)(as + r0*BKP + kk + t4);
                af[mt][0] = p[0];
                af[mt][1] = p[8*BKP];
                af[mt][2] = p[4];
                af[mt][3] = p[8*BKP + 4];
            }
            #pragma unroll
            for (int nt = 0; nt < 8; nt++) {
                int n0 = wc + nt*8 + g8;
                const uint32_t* p = (const uint32_t*)(bs + n0*BKP + kk + t4);
                bf[nt][0] = p[0];
                bf[nt][1] = p[4];
            }
            #pragma unroll
            for (int mt = 0; mt < 4; mt++)
                #pragma unroll
                for (int nt = 0; nt < 8; nt++)
                    mma_tf32_16n8k8(acc[mt][nt], af[mt], bf[nt]);
        }
        __syncthreads();
    }

    /* epilogue: fragment -> float2 stores (ldc even, col even -> aligned) */
    #pragma unroll
    for (int mt = 0; mt < 4; mt++) {
        int r0 = mBase + wr + mt*16 + g8;
        #pragma unroll
        for (int nt = 0; nt < 8; nt++) {
            int cc = nBase + wc + nt*8 + t4*2;
            if (cc < Nvalid) {
                float bx = bias ? bias[cc]   : 0.f;
                float by = bias ? bias[cc+1] : 0.f;
                float2 v0 = make_float2(acc[mt][nt][0] + bx, acc[mt][nt][1] + by);
                float2 v1 = make_float2(acc[mt][nt][2] + bx, acc[mt][nt][3] + by);
                *(float2*)(C + (size_t)r0*ldc + cc)     = v0;
                *(float2*)(C + (size_t)(r0+8)*ldc + cc) = v1;
            }
        }
    }
}

/* =================== misc kernels =================== */
__global__ void k_gather(const float* __restrict__ hs, const int* __restrict__ pairs) {
    int p = blockIdx.x;
    int l0 = pairs[p*2 + 0];
    int r0 = pairs[p*2 + 1];
    int b  = p / NP;
    const float* hl = hs + ((size_t)b*SEQ + l0)*DIM;
    const float* hr = hs + ((size_t)b*SEQ + r0)*DIM;
    float* dst = g_lr + (size_t)p*K1;
    for (int k = threadIdx.x; k < DIM; k += blockDim.x) {
        dst[k]       = hl[k];
        dst[DIM + k] = hr[k];
    }
}

__global__ void k_posproj(const float* __restrict__ pos, const float* __restrict__ W1,
                          const float* __restrict__ b1) {
    __shared__ float sp[PE];
    int l = blockIdx.x;
    for (int t = threadIdx.x; t < PE; t += blockDim.x) sp[t] = pos[l*PE + t];
    __syncthreads();
    int j = threadIdx.x;
    float acc = b1[j];
    const float* w = W1 + (size_t)K1*DIM + j;
    #pragma unroll 4
    for (int t = 0; t < PE; t++) acc += sp[t] * w[(size_t)t*DIM];
    g_P[l*DIM + j] = acc;
}

__global__ void k_reduce4() {
    int i = blockIdx.x*blockDim.x + threadIdx.x;
    g_A[i] = g_Apart[i] + g_Apart[NB*DIM + i] + g_Apart[2*NB*DIM + i] + g_Apart[3*NB*DIM + i];
}

__global__ void k_transpose(const float* __restrict__ in, float* __restrict__ out, int R, int C) {
    __shared__ float t[32][33];
    int c0 = blockIdx.x*32, r0 = blockIdx.y*32;
    for (int dy = threadIdx.y; dy < 32; dy += 8)
        t[dy][threadIdx.x] = in[(size_t)(r0+dy)*C + c0 + threadIdx.x];
    __syncthreads();
    for (int dy = threadIdx.y; dy < 32; dy += 8)
        out[(size_t)(c0+dy)*R + r0 + threadIdx.x] = t[threadIdx.x][dy];
}

__device__ __forceinline__ void block_reduce2(float& s, float& sq) {
    __shared__ float ss[8], ssq[8];
    #pragma unroll
    for (int o = 16; o > 0; o >>= 1) {
        s  += __shfl_xor_sync(0xffffffffu, s,  o);
        sq += __shfl_xor_sync(0xffffffffu, sq, o);
    }
    int w = threadIdx.x >> 5;
    if ((threadIdx.x & 31) == 0) { ss[w] = s; ssq[w] = sq; }
    __syncthreads();
    s = 0.f; sq = 0.f;
    #pragma unroll
    for (int i = 0; i < 8; i++) { s += ss[i]; sq += ssq[i]; }
}

__global__ void k_fuse1(const float* __restrict__ g1, const float* __restrict__ be1) {
    int r = blockIdx.x;
    int p = r / SPAN, l = r % SPAN;
    const float* Ap = g_A + (size_t)p*DIM;
    const float* Pl = g_P + (size_t)l*DIM;
    float v[3];
    float s = 0.f, sq = 0.f;
    int j0 = threadIdx.x;
    #pragma unroll
    for (int t = 0; t < 3; t++) {
        int j = j0 + t*256;
        float x = gelu_exact(Ap[j] + Pl[j]);
        v[t] = x; s += x; sq += x*x;
    }
    block_reduce2(s, sq);
    float mean = s * (1.0f/DIM);
    float var  = sq * (1.0f/DIM) - mean*mean;
    float rstd = rsqrtf(var + 1e-12f);
    float* out = g_h1 + (size_t)r*DIM;
    #pragma unroll
    for (int t = 0; t < 3; t++) {
        int j = j0 + t*256;
        out[j] = (v[t] - mean) * rstd * g1[j] + be1[j];
    }
}

__global__ void k_gelu_ln(const float* __restrict__ in, float* __restrict__ out,
                          const float* __restrict__ g, const float* __restrict__ be) {
    int r = blockIdx.x;
    const float* ip = in + (size_t)r*DIM;
    float v[3];
    float s = 0.f, sq = 0.f;
    int j0 = threadIdx.x;
    #pragma unroll
    for (int t = 0; t < 3; t++) {
        int j = j0 + t*256;
        float x = gelu_exact(ip[j]);
        v[t] = x; s += x; sq += x*x;
    }
    block_reduce2(s, sq);
    float mean = s * (1.0f/DIM);
    float var  = sq * (1.0f/DIM) - mean*mean;
    float rstd = rsqrtf(var + 1e-12f);
    float* op = out + (size_t)r*DIM;
    #pragma unroll
    for (int t = 0; t < 3; t++) {
        int j = j0 + t*256;
        op[j] = (v[t] - mean) * rstd * g[j] + be[j];
    }
}

/* SIMT SGEMM kept for GEMM1 (small, split-K) */
template<int BM, int BN, int BK, int TM, int TN>
__global__ void __launch_bounds__((BM/TM)*(BN/TN))
sgemm(int M, int N, int K,
      const float* __restrict__ A, int lda,
      const float* __restrict__ Bm, int ldb,
      float* __restrict__ C, int ldc,
      const float* __restrict__ bias, int czstride) {
    constexpr int NT_ = (BM/TM)*(BN/TN);
    constexpr int AS = BM + 4;
    constexpr int BSs = BN + 4;
    __shared__ __align__(16) float As[BK*AS];
    __shared__ __align__(16) float Bs[BK*BSs];

    const int mBase = blockIdx.y * BM;
    const int nBase = blockIdx.x * BN;
    const int k0    = blockIdx.z * K;
    C += (size_t)blockIdx.z * czstride;

    const int ty = threadIdx.x / (BN/TN);
    const int tx = threadIdx.x % (BN/TN);

    float acc[TM][TN];
    #pragma unroll
    for (int i = 0; i < TM; i++)
        #pragma unroll
        for (int j = 0; j < TN; j++) acc[i][j] = 0.f;

    constexpr int KV = BK/4;

    for (int kt = 0; kt < K; kt += BK) {
        {
            int k4 = (threadIdx.x % KV) * 4;
            #pragma unroll
            for (int m = threadIdx.x / KV; m < BM; m += NT_/KV) {
                float4 v = *(const float4*)(A + (size_t)(mBase + m)*lda + (k0 + kt + k4));
                As[(k4+0)*AS + m] = v.x;
                As[(k4+1)*AS + m] = v.y;
                As[(k4+2)*AS + m] = v.z;
                As[(k4+3)*AS + m] = v.w;
            }
        }
        {
            constexpr int NV = BN/4;
            int n4 = (threadIdx.x % NV) * 4;
            #pragma unroll
            for (int k = threadIdx.x / NV; k < BK; k += NT_/NV) {
                float4 v = *(const float4*)(Bm + (size_t)(k0 + kt + k)*ldb + (nBase + n4));
                *(float4*)&Bs[k*BSs + n4] = v;
            }
        }
        __syncthreads();

        #pragma unroll
        for (int kk = 0; kk < BK; kk++) {
            float a[TM], b[TN];
            #pragma unroll
            for (int i = 0; i < TM; i += 4)
                *(float4*)&a[i] = *(const float4*)&As[kk*AS + ty*TM + i];
            #pragma unroll
            for (int j = 0; j < TN; j += 4)
                *(float4*)&b[j] = *(const float4*)&Bs[kk*BSs + tx*TN + j];
            #pragma unroll
            for (int i = 0; i < TM; i++)
                #pragma unroll
                for (int j = 0; j < TN; j++)
                    acc[i][j] += a[i] * b[j];
        }
        __syncthreads();
    }

    #pragma unroll
    for (int i = 0; i < TM; i++) {
        int gm = mBase + ty*TM + i;
        float* crow = C + (size_t)gm*ldc;
        #pragma unroll
        for (int j = 0; j < TN; j += 4) {
            int gn = nBase + tx*TN + j;
            float4 v;
            v.x = acc[i][j+0] + (bias ? bias[gn+0] : 0.f);
            v.y = acc[i][j+1] + (bias ? bias[gn+1] : 0.f);
            v.z = acc[i][j+2] + (bias ? bias[gn+2] : 0.f);
            v.w = acc[i][j+3] + (bias ? bias[gn+3] : 0.f);
            *(float4*)(crow + gn) = v;
        }
    }
}

/* ---------------- host launch ---------------- */
extern "C" void kernel_launch(void* const* d_in, const int* in_sizes, int n_in,
                              void* d_out, int out_size) {
    const float* hs    = (const float*)d_in[0];
    const int*   pairs = (const int*)  d_in[1];
    const float* pos   = (const float*)d_in[2];
    const float* W1    = (const float*)d_in[3];
    const float* b1    = (const float*)d_in[4];
    const float* g1    = (const float*)d_in[5];
    const float* be1   = (const float*)d_in[6];
    const float* W2    = (const float*)d_in[7];
    const float* b2    = (const float*)d_in[8];
    const float* g2    = (const float*)d_in[9];
    const float* be2   = (const float*)d_in[10];
    const float* Wp    = (const float*)d_in[11];
    const float* bp    = (const float*)d_in[12];
    const float* Wdec  = (const float*)d_in[13];
    float* out = (float*)d_out;
    (void)in_sizes; (void)n_in; (void)out_size;

    float *p_lr, *p_h1, *p_pre2, *p_h2, *p_h3, *p_W2T, *p_WpT;
    cudaGetSymbolAddress((void**)&p_lr,   g_lr);
    cudaGetSymbolAddress((void**)&p_h1,   g_h1);
    cudaGetSymbolAddress((void**)&p_pre2, g_pre2);
    cudaGetSymbolAddress((void**)&p_h2,   g_h2);
    cudaGetSymbolAddress((void**)&p_h3,   g_h3);
    cudaGetSymbolAddress((void**)&p_W2T,  g_W2T);
    cudaGetSymbolAddress((void**)&p_WpT,  g_WpT);

    const int MSMEM = 4 * 128 * BKP * 4;   /* 2 stages x (A+B) = 73728 B */
    cudaFuncSetAttribute(mgemm, cudaFuncAttributeMaxDynamicSharedMemorySize, MSMEM);

    /* 0) transposes so all tensor GEMMs are NT */
    k_transpose<<<dim3(DIM/32, DIM/32), dim3(32,8)>>>(W2, p_W2T, DIM, DIM);
    k_transpose<<<dim3(EMB/32, DIM/32), dim3(32,8)>>>(Wp, p_WpT, DIM, EMB);

    /* 1) gather [lh, rh] rows */
    k_gather<<<NB, 256>>>(hs, pairs);

    /* 2) P = pos_emb @ W1c + b1 */
    k_posproj<<<SPAN, DIM>>>(pos, W1, b1);

    /* 3) A = g_lr @ W1[0:1536]  (fp32 split-K x4) */
    {
        float* p_Apart; cudaGetSymbolAddress((void**)&p_Apart, g_Apart);
        sgemm<64,128,32,8,8><<<dim3(DIM/128, NB/64, 4), 128>>>(
            NB, DIM, K1/4, p_lr, K1, W1, DIM, p_Apart, DIM, nullptr, NB*DIM);
        k_reduce4<<<(NB*DIM)/256, 256>>>();
    }

    /* 4) h1 = LN(gelu(A + P)) */
    k_fuse1<<<NR, 256>>>(g1, be1);

    /* 5) pre2 = h1 @ W2 + b2 (tf32 mma), h2 = LN(gelu(pre2)) */
    mgemm<<<dim3(DIM/128, NR/128), 128, MSMEM>>>(
        DIM, p_h1, DIM, p_W2T, DIM, DIM, p_pre2, DIM, b2);
    k_gelu_ln<<<NR, 256>>>(p_pre2, p_h2, g2, be2);

    /* 6) h3 = h2 @ Wp + bp (tf32 mma) */
    mgemm<<<dim3(EMB/128, NR/128), 128, MSMEM>>>(
        DIM, p_h2, DIM, p_WpT, DIM, EMB, p_h3, EMB, bp);

    /* 7) out = h3 @ Wdec^T (tf32 mma, M=5120 N=30522 K=128) */
    mgemm<<<dim3((VOCAB + 127)/128, NR/128), 128, MSMEM>>>(
        EMB, p_h3, EMB, Wdec, EMB, VOCAB, out, VOCAB, nullptr);
}